// round 7
// baseline (speedup 1.0000x reference)
#include <cuda_runtime.h>

#define AR    9
#define HW    48
#define NB    4
#define NCI   64
#define NCO   64
#define ND    9          // integer disparities -4..4
#define HIN   432
#define GUARD 144        // 16 macro-pixels * 9 (max shift m*(kw-4) = 4*4 = 16)
#define XSW   (HIN + 2*GUARD)   // 720
#define CC    8          // ci chunk

// Scratch (device globals: no allocation allowed)
__device__ float g_wT[9 * NCI * 9 * NCO];                    // [kh][ci][kw][co]  1.3 MB
__device__ float g_conv[(size_t)ND * NB * NCO * HW * HW];    // 21.2 MB

// ---------------------------------------------------------------------------
// Kernel 0: weight transpose [co][ci][kh][kw] -> [kh][ci][kw][co]
// ---------------------------------------------------------------------------
__global__ void wt_kernel(const float* __restrict__ w) {
    int idx = blockIdx.x * 256 + threadIdx.x;
    if (idx >= NCO * NCI * 81) return;
    int kw = idx % 9; int t = idx / 9;
    int kh = t % 9;   t /= 9;
    int ci = t % NCI; int co = t / NCI;
    g_wT[((kh * NCI + ci) * 9 + kw) * NCO + co] = w[idx];
}

__device__ __forceinline__ void fma2(unsigned long long& d,
                                     unsigned long long a,
                                     unsigned long long b) {
    asm("fma.rn.f32x2 %0, %1, %2, %0;" : "+l"(d) : "l"(a), "l"(b));
}

// ---------------------------------------------------------------------------
// Kernel 1: 9 dilated convs, reformulated as macro-shift taps.
// grid = (oh=48, b=4, dIdx=9), block = 128 threads.
// thread tile: 8 co x 3 ow ; f32x2 pairs along co (w pairs contiguous in smem).
// ---------------------------------------------------------------------------
__global__ void __launch_bounds__(128) conv_kernel(const float* __restrict__ x) {
    __shared__ __align__(16) float xs[CC][XSW];      // x rows with zero guards
    __shared__ __align__(16) float ws[CC][9][NCO];   // [ci][kw][co]

    const int oh   = blockIdx.x;
    const int b    = blockIdx.y;
    const int dIdx = blockIdx.z;
    const int d    = dIdx - 4;
    const int m    = d < 0 ? -d : d;
    const bool flip = (d > 0);

    const int t   = threadIdx.x;
    const int ow0 = (t & 15) * 3;   // 16 ow-groups x 3
    const int co0 = (t >> 4) * 8;   // 8 co-groups x 8

    // Zero whole xs once; valid region [GUARD, GUARD+432) is fully rewritten
    // each stage, guards stay zero forever.
    for (int i = t; i < CC * XSW; i += 128) (&xs[0][0])[i] = 0.f;

    int xoff[9];
#pragma unroll
    for (int kw = 0; kw < 9; kw++) {
        int sub = flip ? (8 - kw) : kw;
        xoff[kw] = GUARD + 9 * (m * (kw - 4)) + sub;
    }

    unsigned long long acc[3][4];
#pragma unroll
    for (int j = 0; j < 3; j++)
#pragma unroll
        for (int p = 0; p < 4; p++) acc[j][p] = 0ull;

    __syncthreads();

    for (int kh = 0; kh < 9; kh++) {
        int ihm = oh + m * (kh - 4);
        if (ihm < 0 || ihm >= HW) continue;   // block-uniform: safe with syncs
        int sub_h = flip ? (8 - kh) : kh;
        int ih = 9 * ihm + sub_h;

        for (int c0 = 0; c0 < NCI; c0 += CC) {
            __syncthreads();
            {   // stage x rows: 8 rows x 432 floats (108 float4 each)
                int r = t >> 4, lane = t & 15;
                const float4* src =
                    (const float4*)(x + ((size_t)(b * NCI + c0 + r) * HIN + ih) * HIN);
                float4* dst = (float4*)(&xs[r][GUARD]);
#pragma unroll
                for (int k = 0; k < 7; k++) {
                    int c = lane + 16 * k;
                    if (c < 108) dst[c] = src[c];
                }
            }
            {   // stage weights: 8*9*64 floats = 1152 float4, coalesced
                const float4* src =
                    (const float4*)(g_wT + (size_t)((kh * NCI + c0) * 9) * NCO);
                float4* dst = (float4*)(&ws[0][0][0]);
#pragma unroll
                for (int k = 0; k < 9; k++) dst[t + 128 * k] = src[t + 128 * k];
            }
            __syncthreads();

            for (int ci = 0; ci < CC; ci++) {
                const float* xr = xs[ci] + 9 * ow0;
#pragma unroll
                for (int kw = 0; kw < 9; kw++) {
                    const ulonglong2* wp = (const ulonglong2*)(&ws[ci][kw][co0]);
                    ulonglong2 wA = wp[0];
                    ulonglong2 wB = wp[1];
#pragma unroll
                    for (int j = 0; j < 3; j++) {
                        float xv = xr[xoff[kw] + 9 * j];
                        unsigned long long xx;
                        asm("mov.b64 %0, {%1, %1};" : "=l"(xx) : "f"(xv));
                        fma2(acc[j][0], xx, wA.x);
                        fma2(acc[j][1], xx, wA.y);
                        fma2(acc[j][2], xx, wB.x);
                        fma2(acc[j][3], xx, wB.y);
                    }
                }
            }
        }
    }

    // write conv result [dIdx][b][co][oh][ow]
    float* outp = g_conv +
        (((size_t)(dIdx * NB + b) * NCO + co0) * HW + oh) * HW + ow0;
#pragma unroll
    for (int p = 0; p < 4; p++)
#pragma unroll
        for (int j = 0; j < 3; j++) {
            float lo, hi;
            asm("mov.b64 {%0, %1}, %2;" : "=f"(lo), "=f"(hi) : "l"(acc[j][p]));
            outp[(size_t)(2 * p) * HW * HW + j]     = lo;
            outp[(size_t)(2 * p + 1) * HW * HW + j] = hi;
        }
}

// ---------------------------------------------------------------------------
// Kernel 2: assemble cost volume [B, CO, 68, 48, 48].
// i even -> zeros; i odd -> 0.5*(conv[p] + conv[p+1]); 4 replicas per slice.
// ---------------------------------------------------------------------------
__global__ void assemble_kernel(float* __restrict__ out) {
    const int total = NB * NCO * 17 * HW * (HW / 4);   // 2,506,752
    int idx = blockIdx.x * 256 + threadIdx.x;
    if (idx >= total) return;
    int w4 = idx % 12; int t = idx / 12;
    int oh = t % 48;   t /= 48;
    int i  = t % 17;   t /= 17;
    int co = t % 64;   int b = t / 64;

    float4 val = make_float4(0.f, 0.f, 0.f, 0.f);
    if (i & 1) {
        int p = (i - 1) >> 1;   // dIdx of d_low
        const float* base1 = g_conv +
            (((size_t)(p * NB + b) * NCO + co) * HW + oh) * HW;
        const float* base2 = base1 + (size_t)NB * NCO * HW * HW;
        float4 a = ((const float4*)base1)[w4];
        float4 c = ((const float4*)base2)[w4];
        val = make_float4(0.5f * (a.x + c.x), 0.5f * (a.y + c.y),
                          0.5f * (a.z + c.z), 0.5f * (a.w + c.w));
    }
    float4* o = (float4*)(out +
        ((((size_t)b * NCO + co) * 68 + 4 * i) * HW + oh) * HW) + w4;
    o[0]    = val;   // replicas: dd stride = 48*48 floats = 576 float4
    o[576]  = val;
    o[1152] = val;
    o[1728] = val;
}

// ---------------------------------------------------------------------------
extern "C" void kernel_launch(void* const* d_in, const int* in_sizes, int n_in,
                              void* d_out, int out_size) {
    const float* x = (const float*)d_in[0];
    const float* w = (const float*)d_in[1];
    if (n_in >= 2 && in_sizes[0] < in_sizes[1]) {   // robustness: x is the big one
        const float* tmp = x; x = w; w = tmp;
    }
    wt_kernel<<<(NCO * NCI * 81 + 255) / 256, 256>>>(w);
    conv_kernel<<<dim3(HW, NB, ND), 128>>>(x);
    assemble_kernel<<<(NB * NCO * 17 * HW * (HW / 4) + 255) / 256, 256>>>((float*)d_out);
}

// round 9
// speedup vs baseline: 1.0046x; 1.0046x over previous
#include <cuda_runtime.h>

#define AR    9
#define HW    48
#define NB    4
#define NCI   64
#define NCO   64
#define ND    9          // integer disparities -4..4
#define HIN   432
#define GUARD 144        // 16 macro-pixels * 9 (max shift m*(kw-4) = 4*4 = 16)
#define XSW   (HIN + 2*GUARD)   // 720
#define CC    8          // ci chunk

// Scratch (device globals: no allocation allowed)
__device__ float g_wT[9 * NCI * 9 * NCO];                    // [kh][ci][kw][co]  1.3 MB
__device__ float g_conv[(size_t)ND * NB * NCO * HW * HW];    // 21.2 MB

// ---------------------------------------------------------------------------
// Kernel 0: weight transpose [co][ci][kh][kw] -> [kh][ci][kw][co]
// ---------------------------------------------------------------------------
__global__ void wt_kernel(const float* __restrict__ w) {
    int idx = blockIdx.x * 256 + threadIdx.x;
    if (idx >= NCO * NCI * 81) return;
    int kw = idx % 9; int t = idx / 9;
    int kh = t % 9;   t /= 9;
    int ci = t % NCI; int co = t / NCI;
    g_wT[((kh * NCI + ci) * 9 + kw) * NCO + co] = w[idx];
}

__device__ __forceinline__ void fma2(unsigned long long& d,
                                     unsigned long long a,
                                     unsigned long long b) {
    asm("fma.rn.f32x2 %0, %1, %2, %0;" : "+l"(d) : "l"(a), "l"(b));
}

// ---------------------------------------------------------------------------
// Kernel 1: 9 dilated convs, reformulated as macro-shift taps.
// grid = (oh=48, b=4, dIdx=9), block = 128 threads.
// thread tile: 8 co x 3 ow ; f32x2 pairs along co (w pairs contiguous in smem).
// ---------------------------------------------------------------------------
__global__ void __launch_bounds__(128) conv_kernel(const float* __restrict__ x) {
    __shared__ __align__(16) float xs[CC][XSW];      // x rows with zero guards
    __shared__ __align__(16) float ws[CC][9][NCO];   // [ci][kw][co]

    const int oh   = blockIdx.x;
    const int b    = blockIdx.y;
    const int dIdx = blockIdx.z;
    const int d    = dIdx - 4;
    const int m    = d < 0 ? -d : d;
    const bool flip = (d > 0);

    const int t   = threadIdx.x;
    const int ow0 = (t & 15) * 3;   // 16 ow-groups x 3
    const int co0 = (t >> 4) * 8;   // 8 co-groups x 8

    // Zero whole xs once; valid region [GUARD, GUARD+432) is fully rewritten
    // each stage, guards stay zero forever.
    for (int i = t; i < CC * XSW; i += 128) (&xs[0][0])[i] = 0.f;

    int xoff[9];
#pragma unroll
    for (int kw = 0; kw < 9; kw++) {
        int sub = flip ? (8 - kw) : kw;
        xoff[kw] = GUARD + 9 * (m * (kw - 4)) + sub;
    }

    unsigned long long acc[3][4];
#pragma unroll
    for (int j = 0; j < 3; j++)
#pragma unroll
        for (int p = 0; p < 4; p++) acc[j][p] = 0ull;

    __syncthreads();

    for (int kh = 0; kh < 9; kh++) {
        int ihm = oh + m * (kh - 4);
        if (ihm < 0 || ihm >= HW) continue;   // block-uniform: safe with syncs
        int sub_h = flip ? (8 - kh) : kh;
        int ih = 9 * ihm + sub_h;

        for (int c0 = 0; c0 < NCI; c0 += CC) {
            __syncthreads();
            {   // stage x rows: 8 rows x 432 floats (108 float4 each)
                int r = t >> 4, lane = t & 15;
                const float4* src =
                    (const float4*)(x + ((size_t)(b * NCI + c0 + r) * HIN + ih) * HIN);
                float4* dst = (float4*)(&xs[r][GUARD]);
#pragma unroll
                for (int k = 0; k < 7; k++) {
                    int c = lane + 16 * k;
                    if (c < 108) dst[c] = src[c];
                }
            }
            {   // stage weights: 8*9*64 floats = 1152 float4, coalesced
                const float4* src =
                    (const float4*)(g_wT + (size_t)((kh * NCI + c0) * 9) * NCO);
                float4* dst = (float4*)(&ws[0][0][0]);
#pragma unroll
                for (int k = 0; k < 9; k++) dst[t + 128 * k] = src[t + 128 * k];
            }
            __syncthreads();

            for (int ci = 0; ci < CC; ci++) {
                const float* xr = xs[ci] + 9 * ow0;
#pragma unroll
                for (int kw = 0; kw < 9; kw++) {
                    const ulonglong2* wp = (const ulonglong2*)(&ws[ci][kw][co0]);
                    ulonglong2 wA = wp[0];
                    ulonglong2 wB = wp[1];
#pragma unroll
                    for (int j = 0; j < 3; j++) {
                        float xv = xr[xoff[kw] + 9 * j];
                        unsigned long long xx;
                        asm("mov.b64 %0, {%1, %1};" : "=l"(xx) : "f"(xv));
                        fma2(acc[j][0], xx, wA.x);
                        fma2(acc[j][1], xx, wA.y);
                        fma2(acc[j][2], xx, wB.x);
                        fma2(acc[j][3], xx, wB.y);
                    }
                }
            }
        }
    }

    // write conv result [dIdx][b][co][oh][ow]
    float* outp = g_conv +
        (((size_t)(dIdx * NB + b) * NCO + co0) * HW + oh) * HW + ow0;
#pragma unroll
    for (int p = 0; p < 4; p++)
#pragma unroll
        for (int j = 0; j < 3; j++) {
            float lo, hi;
            asm("mov.b64 {%0, %1}, %2;" : "=f"(lo), "=f"(hi) : "l"(acc[j][p]));
            outp[(size_t)(2 * p) * HW * HW + j]     = lo;
            outp[(size_t)(2 * p + 1) * HW * HW + j] = hi;
        }
}

// ---------------------------------------------------------------------------
// Kernel 2: assemble cost volume [B, CO, 68, 48, 48].
// i even -> zeros; i odd -> 0.5*(conv[p] + conv[p+1]); 4 replicas per slice.
// ---------------------------------------------------------------------------
__global__ void assemble_kernel(float* __restrict__ out) {
    const int total = NB * NCO * 17 * HW * (HW / 4);   // 2,506,752
    int idx = blockIdx.x * 256 + threadIdx.x;
    if (idx >= total) return;
    int w4 = idx % 12; int t = idx / 12;
    int oh = t % 48;   t /= 48;
    int i  = t % 17;   t /= 17;
    int co = t % 64;   int b = t / 64;

    float4 val = make_float4(0.f, 0.f, 0.f, 0.f);
    if (i & 1) {
        int p = (i - 1) >> 1;   // dIdx of d_low
        const float* base1 = g_conv +
            (((size_t)(p * NB + b) * NCO + co) * HW + oh) * HW;
        const float* base2 = base1 + (size_t)NB * NCO * HW * HW;
        float4 a = ((const float4*)base1)[w4];
        float4 c = ((const float4*)base2)[w4];
        val = make_float4(0.5f * (a.x + c.x), 0.5f * (a.y + c.y),
                          0.5f * (a.z + c.z), 0.5f * (a.w + c.w));
    }
    float4* o = (float4*)(out +
        ((((size_t)b * NCO + co) * 68 + 4 * i) * HW + oh) * HW) + w4;
    o[0]    = val;   // replicas: dd stride = 48*48 floats = 576 float4
    o[576]  = val;
    o[1152] = val;
    o[1728] = val;
}

// ---------------------------------------------------------------------------
extern "C" void kernel_launch(void* const* d_in, const int* in_sizes, int n_in,
                              void* d_out, int out_size) {
    const float* x = (const float*)d_in[0];
    const float* w = (const float*)d_in[1];
    if (n_in >= 2 && in_sizes[0] < in_sizes[1]) {   // robustness: x is the big one
        const float* tmp = x; x = w; w = tmp;
    }
    wt_kernel<<<(NCO * NCI * 81 + 255) / 256, 256>>>(w);
    conv_kernel<<<dim3(HW, NB, ND), 128>>>(x);
    assemble_kernel<<<(NB * NCO * 17 * HW * (HW / 4) + 255) / 256, 256>>>((float*)d_out);
}

// round 10
// speedup vs baseline: 1.0099x; 1.0053x over previous
#include <cuda_runtime.h>

#define AR    9
#define HW    48
#define NB    4
#define NCI   64
#define NCO   64
#define ND    9          // integer disparities -4..4
#define HIN   432
#define GUARD 144        // 16 macro-pixels * 9 (max shift m*(kw-4) = 4*4 = 16)
#define XSW   (HIN + 2*GUARD)   // 720
#define CC    8          // ci chunk

// Scratch (device globals: no allocation allowed)
__device__ float g_wT[9 * NCI * 9 * NCO];                    // [kh][ci][kw][co]  1.3 MB
__device__ float g_conv[(size_t)ND * NB * NCO * HW * HW];    // 21.2 MB

// ---------------------------------------------------------------------------
// Kernel 0: weight transpose [co][ci][kh][kw] -> [kh][ci][kw][co]
// ---------------------------------------------------------------------------
__global__ void wt_kernel(const float* __restrict__ w) {
    int idx = blockIdx.x * 256 + threadIdx.x;
    if (idx >= NCO * NCI * 81) return;
    int kw = idx % 9; int t = idx / 9;
    int kh = t % 9;   t /= 9;
    int ci = t % NCI; int co = t / NCI;
    g_wT[((kh * NCI + ci) * 9 + kw) * NCO + co] = w[idx];
}

__device__ __forceinline__ void fma2(unsigned long long& d,
                                     unsigned long long a,
                                     unsigned long long b) {
    asm("fma.rn.f32x2 %0, %1, %2, %0;" : "+l"(d) : "l"(a), "l"(b));
}

// ---------------------------------------------------------------------------
// Kernel 1: 9 dilated convs, reformulated as macro-shift taps.
// grid = (oh=48, b=4, dIdx=9), block = 128 threads.
// thread tile: 8 co x 3 ow ; f32x2 pairs along co (w pairs contiguous in smem).
// ---------------------------------------------------------------------------
__global__ void __launch_bounds__(128) conv_kernel(const float* __restrict__ x) {
    __shared__ __align__(16) float xs[CC][XSW];      // x rows with zero guards
    __shared__ __align__(16) float ws[CC][9][NCO];   // [ci][kw][co]

    const int oh   = blockIdx.x;
    const int b    = blockIdx.y;
    const int dIdx = blockIdx.z;
    const int d    = dIdx - 4;
    const int m    = d < 0 ? -d : d;
    const bool flip = (d > 0);

    const int t   = threadIdx.x;
    const int ow0 = (t & 15) * 3;   // 16 ow-groups x 3
    const int co0 = (t >> 4) * 8;   // 8 co-groups x 8

    // Zero whole xs once; valid region [GUARD, GUARD+432) is fully rewritten
    // each stage, guards stay zero forever.
    for (int i = t; i < CC * XSW; i += 128) (&xs[0][0])[i] = 0.f;

    int xoff[9];
#pragma unroll
    for (int kw = 0; kw < 9; kw++) {
        int sub = flip ? (8 - kw) : kw;
        xoff[kw] = GUARD + 9 * (m * (kw - 4)) + sub;
    }

    unsigned long long acc[3][4];
#pragma unroll
    for (int j = 0; j < 3; j++)
#pragma unroll
        for (int p = 0; p < 4; p++) acc[j][p] = 0ull;

    __syncthreads();

    for (int kh = 0; kh < 9; kh++) {
        int ihm = oh + m * (kh - 4);
        if (ihm < 0 || ihm >= HW) continue;   // block-uniform: safe with syncs
        int sub_h = flip ? (8 - kh) : kh;
        int ih = 9 * ihm + sub_h;

        for (int c0 = 0; c0 < NCI; c0 += CC) {
            __syncthreads();
            {   // stage x rows: 8 rows x 432 floats (108 float4 each)
                int r = t >> 4, lane = t & 15;
                const float4* src =
                    (const float4*)(x + ((size_t)(b * NCI + c0 + r) * HIN + ih) * HIN);
                float4* dst = (float4*)(&xs[r][GUARD]);
#pragma unroll
                for (int k = 0; k < 7; k++) {
                    int c = lane + 16 * k;
                    if (c < 108) dst[c] = src[c];
                }
            }
            {   // stage weights: 8*9*64 floats = 1152 float4, coalesced
                const float4* src =
                    (const float4*)(g_wT + (size_t)((kh * NCI + c0) * 9) * NCO);
                float4* dst = (float4*)(&ws[0][0][0]);
#pragma unroll
                for (int k = 0; k < 9; k++) dst[t + 128 * k] = src[t + 128 * k];
            }
            __syncthreads();

            for (int ci = 0; ci < CC; ci++) {
                const float* xr = xs[ci] + 9 * ow0;
#pragma unroll
                for (int kw = 0; kw < 9; kw++) {
                    const ulonglong2* wp = (const ulonglong2*)(&ws[ci][kw][co0]);
                    ulonglong2 wA = wp[0];
                    ulonglong2 wB = wp[1];
#pragma unroll
                    for (int j = 0; j < 3; j++) {
                        float xv = xr[xoff[kw] + 9 * j];
                        unsigned long long xx;
                        asm("mov.b64 %0, {%1, %1};" : "=l"(xx) : "f"(xv));
                        fma2(acc[j][0], xx, wA.x);
                        fma2(acc[j][1], xx, wA.y);
                        fma2(acc[j][2], xx, wB.x);
                        fma2(acc[j][3], xx, wB.y);
                    }
                }
            }
        }
    }

    // write conv result [dIdx][b][co][oh][ow]
    float* outp = g_conv +
        (((size_t)(dIdx * NB + b) * NCO + co0) * HW + oh) * HW + ow0;
#pragma unroll
    for (int p = 0; p < 4; p++)
#pragma unroll
        for (int j = 0; j < 3; j++) {
            float lo, hi;
            asm("mov.b64 {%0, %1}, %2;" : "=f"(lo), "=f"(hi) : "l"(acc[j][p]));
            outp[(size_t)(2 * p) * HW * HW + j]     = lo;
            outp[(size_t)(2 * p + 1) * HW * HW + j] = hi;
        }
}

// ---------------------------------------------------------------------------
// Kernel 2: assemble cost volume [B, CO, 68, 48, 48].
// i even -> zeros; i odd -> 0.5*(conv[p] + conv[p+1]); 4 replicas per slice.
// ---------------------------------------------------------------------------
__global__ void assemble_kernel(float* __restrict__ out) {
    const int total = NB * NCO * 17 * HW * (HW / 4);   // 2,506,752
    int idx = blockIdx.x * 256 + threadIdx.x;
    if (idx >= total) return;
    int w4 = idx % 12; int t = idx / 12;
    int oh = t % 48;   t /= 48;
    int i  = t % 17;   t /= 17;
    int co = t % 64;   int b = t / 64;

    float4 val = make_float4(0.f, 0.f, 0.f, 0.f);
    if (i & 1) {
        int p = (i - 1) >> 1;   // dIdx of d_low
        const float* base1 = g_conv +
            (((size_t)(p * NB + b) * NCO + co) * HW + oh) * HW;
        const float* base2 = base1 + (size_t)NB * NCO * HW * HW;
        float4 a = ((const float4*)base1)[w4];
        float4 c = ((const float4*)base2)[w4];
        val = make_float4(0.5f * (a.x + c.x), 0.5f * (a.y + c.y),
                          0.5f * (a.z + c.z), 0.5f * (a.w + c.w));
    }
    float4* o = (float4*)(out +
        ((((size_t)b * NCO + co) * 68 + 4 * i) * HW + oh) * HW) + w4;
    o[0]    = val;   // replicas: dd stride = 48*48 floats = 576 float4
    o[576]  = val;
    o[1152] = val;
    o[1728] = val;
}

// ---------------------------------------------------------------------------
extern "C" void kernel_launch(void* const* d_in, const int* in_sizes, int n_in,
                              void* d_out, int out_size) {
    const float* x = (const float*)d_in[0];
    const float* w = (const float*)d_in[1];
    if (n_in >= 2 && in_sizes[0] < in_sizes[1]) {   // robustness: x is the big one
        const float* tmp = x; x = w; w = tmp;
    }
    wt_kernel<<<(NCO * NCI * 81 + 255) / 256, 256>>>(w);
    conv_kernel<<<dim3(HW, NB, ND), 128>>>(x);
    assemble_kernel<<<(NB * NCO * 17 * HW * (HW / 4) + 255) / 256, 256>>>((float*)d_out);
}

// round 12
// speedup vs baseline: 3.5451x; 3.5102x over previous
#include <cuda_runtime.h>
#include <cuda_fp16.h>
#include <cstdint>

#define HW   48
#define NB   4
#define NCI  64
#define NCO  64
#define ND   9
#define PW   80          // padded SAI width (48 + 2*16)
#define NTILES 36        // 9216 / 256

// ---------------- device scratch (no allocation allowed) -------------------
// padded SAI tensor: [sai(81)][b(4)][ohp(80)][owp(80)][ci(64)] fp16  (265.4 MB)
__device__ __half g_x[(size_t)81 * NB * PW * PW * NCI];
__device__ __half g_w[81 * NCI * NCO];                       // [tap][ci][co]
__device__ float  g_conv[(size_t)ND * NB * NCO * HW * HW];   // 21.2 MB

__device__ __forceinline__ uint32_t smem_u32(const void* p) {
    uint32_t a;
    asm("{ .reg .u64 t; cvta.to.shared.u64 t, %1; cvt.u32.u64 %0, t; }"
        : "=r"(a) : "l"(p));
    return a;
}
__device__ __forceinline__ void cpasync16(uint32_t dst, const void* src) {
    asm volatile("cp.async.cg.shared.global [%0], [%1], 16;"
                 :: "r"(dst), "l"(src) : "memory");
}

// ---------------------------------------------------------------------------
// Kernel A: zero the pad border of g_x (interior is fully rewritten by reorg).
// border cells per (sai,b): 80*80 - 48*48 = 4096 macro-pixels, 128 B each.
// ---------------------------------------------------------------------------
__global__ void padzero_kernel() {
    int idx = blockIdx.x * 256 + threadIdx.x;      // one float4 (8 halfs) each
    const int total = 324 * 4096 * 8;
    if (idx >= total) return;
    int chunk = idx & 7;
    int cell  = (idx >> 3) & 4095;
    int sb    = idx >> 15;                          // sai*4 + b  (0..323)
    int ohp, owp;
    if (cell < 1280)      { ohp = cell / 80;              owp = cell % 80; }
    else if (cell < 2560) { int c = cell - 1280; ohp = 64 + c / 80; owp = c % 80; }
    else { int c = cell - 2560; ohp = 16 + c / 32; int u = c & 31;
           owp = (u < 16) ? u : u + 32; }
    size_t off = (((size_t)sb * (PW * PW)) + ohp * PW + owp) * NCI + chunk * 8;
    *(float4*)(g_x + off) = make_float4(0.f, 0.f, 0.f, 0.f);
}

// ---------------------------------------------------------------------------
// Kernel B: reorg x[b][ci][432][432] -> padded SAI fp16 interior
// ---------------------------------------------------------------------------
__global__ void __launch_bounds__(256) reorg_kernel(const float* __restrict__ x) {
    __shared__ float xs[16][433];
    const int ih = blockIdx.x, b = blockIdx.y;
    const int sh = ih % 9, ohm = ih / 9;
    for (int c0 = 0; c0 < NCI; c0 += 16) {
        if (c0) __syncthreads();
        for (int i = threadIdx.x; i < 16 * 432; i += 256) {
            int ci = i / 432, iw = i - ci * 432;
            xs[ci][iw] = x[((size_t)(b * NCI + c0 + ci) * 432 + ih) * 432 + iw];
        }
        __syncthreads();
        for (int i = threadIdx.x; i < 432 * 8; i += 256) {
            int cp = i & 7; int t2 = i >> 3;
            int owm = t2 % 48, sw = t2 / 48;
            __half h0 = __float2half(xs[2 * cp][owm * 9 + sw]);
            __half h1 = __float2half(xs[2 * cp + 1][owm * 9 + sw]);
            size_t o = (((size_t)(sh * 9 + sw) * NB + b) * (PW * PW)
                        + (size_t)(ohm + 16) * PW + (owm + 16)) * NCI + c0 + 2 * cp;
            *(__half2*)(g_x + o) = __halves2half2(h0, h1);
        }
    }
}

// ---------------------------------------------------------------------------
// Kernel C: weight prep  w[co][ci][kh][kw] -> g_w[tap][ci][co] fp16
// ---------------------------------------------------------------------------
__global__ void wprep_kernel(const float* __restrict__ w) {
    int idx = blockIdx.x * 256 + threadIdx.x;
    if (idx >= 81 * NCI * NCO) return;
    int co = idx & 63, ci = (idx >> 6) & 63, tap = idx >> 12;
    g_w[idx] = __float2half(w[(size_t)co * 5184 + ci * 81 + tap]);
}

// ---------------------------------------------------------------------------
// Kernel D: HMMA implicit-GEMM conv.
// grid (9, 36), 256 thr (8 warps).  CTA tile D[M=256 spatial][N=64 co].
// Warp w: M rows [32w, 32w+32).  81 taps, K=64 per tap.
// Padded SAI => no bounds checks; per-tap address = rowbase + uniform offset.
// cp.async double buffer; ldmatrix A (row-major) + ldmatrix.trans B ([k][n]).
// ---------------------------------------------------------------------------
#define CONV_SMEM (2 * 32768 + 2 * 8192)    // 81920 B
__global__ void __launch_bounds__(256, 1) conv_kernel() {
    extern __shared__ __align__(128) char dsm[];
    const uint32_t smA = smem_u32(dsm);
    const uint32_t smB = smA + 65536u;

    const int dIdx = blockIdx.x, tile = blockIdx.y;
    const int d = dIdx - 4;
    const int m = d < 0 ? -d : d;
    const bool flip = (d > 0);
    const int t = threadIdx.x, lane = t & 31, w = t >> 5;

    // ---- staging address precompute (fixed per thread) ----
    int32_t  srcA[8];   uint32_t dstA[8];
    #pragma unroll
    for (int i = 0; i < 8; i++) {
        int g = t + 256 * i;
        int r = g >> 3, c = g & 7;
        int s = tile * 256 + r;
        int owm = s % 48, ohm = (s / 48) % 48, bb = s / 2304;
        srcA[i] = bb * (PW * PW * 128) + (ohm + 16) * (PW * 128)
                + (owm + 16) * 128 + c * 16;
        dstA[i] = smA + (uint32_t)r * 128u + (uint32_t)((c ^ (r & 7)) << 4);
    }
    int32_t srcB[2]; uint32_t dstB[2];
    #pragma unroll
    for (int i = 0; i < 2; i++) {
        int g = t + 256 * i;
        int ci = g >> 3, c = g & 7;
        srcB[i] = ci * 128 + c * 16;
        dstB[i] = smB + (uint32_t)ci * 128u + (uint32_t)((c ^ (ci & 7)) << 4);
    }

    // ---- ldmatrix lane addresses (relative to buffer base) ----
    uint32_t adA[2][4], adB[4][4];
    #pragma unroll
    for (int j = 0; j < 2; j++)
        #pragma unroll
        for (int kc = 0; kc < 4; kc++) {
            int row = 32 * w + 16 * j + (lane & 15);
            int ch  = kc * 2 + (lane >> 4);
            adA[j][kc] = (uint32_t)(row * 128) + (uint32_t)((ch ^ (row & 7)) << 4);
        }
    #pragma unroll
    for (int kc = 0; kc < 4; kc++)
        #pragma unroll
        for (int q = 0; q < 4; q++) {
            int row = kc * 16 + (lane & 15);
            int ch  = q * 2 + (lane >> 4);
            adB[kc][q] = (uint32_t)(row * 128) + (uint32_t)((ch ^ (row & 7)) << 4);
        }

    float acc[2][8][4];
    #pragma unroll
    for (int j = 0; j < 2; j++)
        #pragma unroll
        for (int nt = 0; nt < 8; nt++)
            #pragma unroll
            for (int k = 0; k < 4; k++) acc[j][nt][k] = 0.f;

    const char* xb = (const char*)g_x;
    const char* wb = (const char*)g_w;

    // stage tap -> buffer bit `pb`
    auto stage = [&](int tap, uint32_t pb) {
        int kh = tap / 9, kw = tap - kh * 9;
        int sh = flip ? 8 - kh : kh, sw = flip ? 8 - kw : kw;
        int32_t tA = (sh * 9 + sw) * (NB * PW * PW * 128)
                   + (m * (kh - 4)) * (PW * 128) + (m * (kw - 4)) * 128;
        uint32_t aoff = pb * 32768u, boff = pb * 8192u;
        #pragma unroll
        for (int i = 0; i < 8; i++)
            cpasync16(dstA[i] + aoff, xb + (ptrdiff_t)(srcA[i] + tA));
        int32_t tB = tap * 8192;
        #pragma unroll
        for (int i = 0; i < 2; i++)
            cpasync16(dstB[i] + boff, wb + (ptrdiff_t)(srcB[i] + tB));
        asm volatile("cp.async.commit_group;" ::: "memory");
    };

    stage(0, 0u);
    for (int tap = 0; tap < 81; tap++) {
        uint32_t buf = (uint32_t)(tap & 1);
        if (tap + 1 < 81) {
            stage(tap + 1, buf ^ 1u);
            asm volatile("cp.async.wait_group 1;" ::: "memory");
        } else {
            asm volatile("cp.async.wait_group 0;" ::: "memory");
        }
        __syncthreads();     // tap's data visible to all warps

        const uint32_t Ab = smA + buf * 32768u;
        const uint32_t Bb = smB + buf * 8192u;
        #pragma unroll
        for (int kc = 0; kc < 4; kc++) {
            uint32_t br[8][2];
            #pragma unroll
            for (int q = 0; q < 4; q++) {
                uint32_t r0, r1, r2, r3;
                asm volatile(
                    "ldmatrix.sync.aligned.m8n8.x4.trans.shared.b16 {%0,%1,%2,%3}, [%4];"
                    : "=r"(r0), "=r"(r1), "=r"(r2), "=r"(r3)
                    : "r"(Bb + adB[kc][q]));
                br[2 * q][0] = r0; br[2 * q][1] = r1;
                br[2 * q + 1][0] = r2; br[2 * q + 1][1] = r3;
            }
            #pragma unroll
            for (int j = 0; j < 2; j++) {
                uint32_t a0, a1, a2, a3;
                asm volatile(
                    "ldmatrix.sync.aligned.m8n8.x4.shared.b16 {%0,%1,%2,%3}, [%4];"
                    : "=r"(a0), "=r"(a1), "=r"(a2), "=r"(a3)
                    : "r"(Ab + adA[j][kc]));
                #pragma unroll
                for (int nt = 0; nt < 8; nt++) {
                    asm volatile(
                        "mma.sync.aligned.m16n8k16.row.col.f32.f16.f16.f32 "
                        "{%0,%1,%2,%3},{%4,%5,%6,%7},{%8,%9},{%0,%1,%2,%3};"
                        : "+f"(acc[j][nt][0]), "+f"(acc[j][nt][1]),
                          "+f"(acc[j][nt][2]), "+f"(acc[j][nt][3])
                        : "r"(a0), "r"(a1), "r"(a2), "r"(a3),
                          "r"(br[nt][0]), "r"(br[nt][1]));
                }
            }
        }
        __syncthreads();     // all warps done reading buf before it is restaged
    }

    // ---- epilogue: scatter acc to g_conv[d][b][co][oh][ow] ----
    #pragma unroll
    for (int j = 0; j < 2; j++) {
        int r0 = 32 * w + 16 * j + (lane >> 2);
        #pragma unroll
        for (int hh = 0; hh < 2; hh++) {
            int s = tile * 256 + r0 + 8 * hh;
            int bb = s / 2304, rem = s % 2304;
            int oh = rem / 48, ow = rem % 48;
            float* p = g_conv + (((size_t)(dIdx * NB + bb) * NCO) * HW + oh) * HW + ow;
            #pragma unroll
            for (int nt = 0; nt < 8; nt++) {
                int co = nt * 8 + (lane & 3) * 2;
                p[(size_t)co * (HW * HW)]       = acc[j][nt][2 * hh];
                p[(size_t)(co + 1) * (HW * HW)] = acc[j][nt][2 * hh + 1];
            }
        }
    }
}

// ---------------------------------------------------------------------------
// Kernel E: assemble cost volume [B, CO, 68, 48, 48].
// ---------------------------------------------------------------------------
__global__ void assemble_kernel(float* __restrict__ out) {
    const int total = NB * NCO * 17 * HW * (HW / 4);
    int idx = blockIdx.x * 256 + threadIdx.x;
    if (idx >= total) return;
    int w4 = idx % 12; int t = idx / 12;
    int oh = t % 48;   t /= 48;
    int i  = t % 17;   t /= 17;
    int co = t % 64;   int b = t / 64;

    float4 val = make_float4(0.f, 0.f, 0.f, 0.f);
    if (i & 1) {
        int p = (i - 1) >> 1;
        const float* base1 = g_conv +
            (((size_t)(p * NB + b) * NCO + co) * HW + oh) * HW;
        const float* base2 = base1 + (size_t)NB * NCO * HW * HW;
        float4 a = ((const float4*)base1)[w4];
        float4 c = ((const float4*)base2)[w4];
        val = make_float4(0.5f * (a.x + c.x), 0.5f * (a.y + c.y),
                          0.5f * (a.z + c.z), 0.5f * (a.w + c.w));
    }
    float4* o = (float4*)(out +
        ((((size_t)b * NCO + co) * 68 + 4 * i) * HW + oh) * HW) + w4;
    o[0]    = val;
    o[576]  = val;
    o[1152] = val;
    o[1728] = val;
}

// ---------------------------------------------------------------------------
extern "C" void kernel_launch(void* const* d_in, const int* in_sizes, int n_in,
                              void* d_out, int out_size) {
    const float* x = (const float*)d_in[0];
    const float* w = (const float*)d_in[1];
    if (n_in >= 2 && in_sizes[0] < in_sizes[1]) {
        const float* tmp = x; x = w; w = tmp;
    }
    cudaFuncSetAttribute(conv_kernel,
                         cudaFuncAttributeMaxDynamicSharedMemorySize, CONV_SMEM);
    padzero_kernel<<<(324 * 4096 * 8 + 255) / 256, 256>>>();
    reorg_kernel<<<dim3(432, NB), 256>>>(x);
    wprep_kernel<<<(81 * NCI * NCO + 255) / 256, 256>>>(w);
    conv_kernel<<<dim3(ND, NTILES), 256, CONV_SMEM>>>();
    assemble_kernel<<<(NB * NCO * 17 * HW * (HW / 4) + 255) / 256, 256>>>((float*)d_out);
}

// round 13
// speedup vs baseline: 4.0974x; 1.1558x over previous
#include <cuda_runtime.h>
#include <cuda_fp16.h>
#include <cstdint>

#define HW   48
#define NB   4
#define NCI  64
#define NCO  64
#define ND   9
#define NTILES 36        // 9216 / 256
#define SAI_STRIDE (NB * 2304 * 128)     // bytes per sub-aperture image

// ---------------- device scratch (no allocation allowed) -------------------
// unpadded SAI tensor: [sai(81)][b(4)][oh(48)][ow(48)][ci(64)] fp16  (95.6 MB)
__device__ __half g_x[(size_t)81 * NB * HW * HW * NCI];
__device__ __half g_w[81 * NCI * NCO];                       // [tap][ci][co]
__device__ float  g_conv[(size_t)ND * NB * NCO * HW * HW];   // 21.2 MB

__device__ __forceinline__ uint32_t smem_u32(const void* p) {
    uint32_t a;
    asm("{ .reg .u64 t; cvta.to.shared.u64 t, %1; cvt.u32.u64 %0, t; }"
        : "=r"(a) : "l"(p));
    return a;
}

// ---------------------------------------------------------------------------
// Kernel B: reorg x[b][ci][432][432] -> SAI fp16 [sai][b][oh][ow][ci]
// ---------------------------------------------------------------------------
__global__ void __launch_bounds__(256) reorg_kernel(const float* __restrict__ x) {
    __shared__ float xs[16][433];
    const int ih = blockIdx.x, b = blockIdx.y;
    const int sh = ih % 9, ohm = ih / 9;
    for (int c0 = 0; c0 < NCI; c0 += 16) {
        if (c0) __syncthreads();
        for (int i = threadIdx.x; i < 16 * 432; i += 256) {
            int ci = i / 432, iw = i - ci * 432;
            xs[ci][iw] = x[((size_t)(b * NCI + c0 + ci) * 432 + ih) * 432 + iw];
        }
        __syncthreads();
        for (int i = threadIdx.x; i < 432 * 8; i += 256) {
            int cp = i & 7; int t2 = i >> 3;
            int owm = t2 % 48, sw = t2 / 48;
            __half h0 = __float2half(xs[2 * cp][owm * 9 + sw]);
            __half h1 = __float2half(xs[2 * cp + 1][owm * 9 + sw]);
            size_t o = (((size_t)(sh * 9 + sw) * NB + b) * (HW * HW)
                        + (size_t)ohm * HW + owm) * NCI + c0 + 2 * cp;
            *(__half2*)(g_x + o) = __halves2half2(h0, h1);
        }
    }
}

// ---------------------------------------------------------------------------
// Kernel C: weight prep  w[co][ci][kh][kw] -> g_w[tap][ci][co] fp16
// ---------------------------------------------------------------------------
__global__ void wprep_kernel(const float* __restrict__ w) {
    int idx = blockIdx.x * 256 + threadIdx.x;
    if (idx >= 81 * NCI * NCO) return;
    int co = idx & 63, ci = (idx >> 6) & 63, tap = idx >> 12;
    g_w[idx] = __float2half(w[(size_t)co * 5184 + ci * 81 + tap]);
}

// ---------------------------------------------------------------------------
// Kernel D: HMMA implicit-GEMM conv.  grid (9, 36), 256 thr (8 warps),
// target 2 CTAs/SM (regs<=128).  CTA tile D[M=256 spatial][N=64 co],
// 81 taps, K=64/tap.  OOB handled by cp.async src_size=0 zero-fill.
// ---------------------------------------------------------------------------
#define CONV_SMEM (2 * 32768 + 2 * 8192)    // 81920 B
__global__ void __launch_bounds__(256, 2) conv_kernel() {
    extern __shared__ __align__(128) char dsm[];
    const uint32_t smA = smem_u32(dsm);
    const uint32_t smB = smA + 65536u;

    const int dIdx = blockIdx.x, tile = blockIdx.y;
    const int d = dIdx - 4;
    const int m = d < 0 ? -d : d;
    const bool flip = (d > 0);
    const int t = threadIdx.x, lane = t & 31, w = t >> 5;

    // ---- staging precompute: thread owns 8 A chunks (16B) + 2 B chunks ----
    int32_t  FA[8];                 // byte offset of chunk in (unshifted) SAI 0
    uint64_t pack_oh = 0, pack_ow = 0;
    #pragma unroll
    for (int i = 0; i < 8; i++) {
        int r = (t >> 3) + 32 * i;
        int s = tile * 256 + r;
        int ow = s % 48, oh = (s / 48) % 48;
        FA[i] = s * 128 + (t & 7) * 16;
        pack_oh |= (uint64_t)oh << (8 * i);
        pack_ow |= (uint64_t)ow << (8 * i);
    }
    const uint32_t dstA0 = smA + (uint32_t)(t >> 3) * 128u
                         + (uint32_t)(((t & 7) ^ ((t >> 3) & 7)) << 4);
    const uint32_t dstB0 = smB + (uint32_t)(t >> 3) * 128u
                         + (uint32_t)(((t & 7) ^ ((t >> 3) & 7)) << 4);

    // ---- ldmatrix lane addresses ----
    uint32_t adA[2][4], adB0[4];
    #pragma unroll
    for (int j = 0; j < 2; j++)
        #pragma unroll
        for (int kc = 0; kc < 4; kc++) {
            int row = 32 * w + 16 * j + (lane & 15);
            int ch  = kc * 2 + (lane >> 4);
            adA[j][kc] = (uint32_t)(row * 128) + (uint32_t)((ch ^ (row & 7)) << 4);
        }
    #pragma unroll
    for (int q = 0; q < 4; q++) {
        int row = lane & 15;
        int ch  = q * 2 + (lane >> 4);
        adB0[q] = (uint32_t)(row * 128) + (uint32_t)((ch ^ (row & 7)) << 4);
    }

    float acc[2][8][4];
    #pragma unroll
    for (int j = 0; j < 2; j++)
        #pragma unroll
        for (int nt = 0; nt < 8; nt++)
            #pragma unroll
            for (int k = 0; k < 4; k++) acc[j][nt][k] = 0.f;

    const char* xb = (const char*)g_x;
    const char* wb = (const char*)g_w + (size_t)t * 16;

    auto stage = [&](int tap, uint32_t pb) {
        int kh = tap / 9, kw = tap - kh * 9;
        int sh = flip ? 8 - kh : kh, sw = flip ? 8 - kw : kw;
        int dh = m * (kh - 4), dw = m * (kw - 4);
        const char* abase = xb + (size_t)(sh * 9 + sw) * SAI_STRIDE
                          + (ptrdiff_t)(dh * 48 + dw) * 128;
        const uint32_t aoff = pb * 32768u;
        #pragma unroll
        for (int i = 0; i < 8; i++) {
            int oh2 = (int)((pack_oh >> (8 * i)) & 255) + dh;
            int ow2 = (int)((pack_ow >> (8 * i)) & 255) + dw;
            bool valid = ((unsigned)oh2 < 48u) & ((unsigned)ow2 < 48u);
            uint32_t sz = valid ? 16u : 0u;
            const char* src = valid ? (abase + FA[i]) : xb;
            asm volatile("cp.async.cg.shared.global [%0], [%1], 16, %2;"
                         :: "r"(dstA0 + aoff + (uint32_t)i * 4096u), "l"(src),
                            "r"(sz) : "memory");
        }
        const char* bsrc = wb + (ptrdiff_t)tap * 8192;
        const uint32_t boff = pb * 8192u;
        #pragma unroll
        for (int i = 0; i < 2; i++)
            asm volatile("cp.async.cg.shared.global [%0], [%1], 16;"
                         :: "r"(dstB0 + boff + (uint32_t)i * 4096u),
                            "l"(bsrc + (ptrdiff_t)i * 4096) : "memory");
        asm volatile("cp.async.commit_group;" ::: "memory");
    };

    stage(0, 0u);
    for (int tap = 0; tap < 81; tap++) {
        uint32_t buf = (uint32_t)(tap & 1);
        if (tap + 1 < 81) {
            stage(tap + 1, buf ^ 1u);
            asm volatile("cp.async.wait_group 1;" ::: "memory");
        } else {
            asm volatile("cp.async.wait_group 0;" ::: "memory");
        }
        __syncthreads();

        const uint32_t Ab = smA + buf * 32768u;
        const uint32_t Bb = smB + buf * 8192u;
        #pragma unroll
        for (int kc = 0; kc < 4; kc++) {
            uint32_t br[8][2];
            #pragma unroll
            for (int q = 0; q < 4; q++) {
                uint32_t r0, r1, r2, r3;
                asm volatile(
                    "ldmatrix.sync.aligned.m8n8.x4.trans.shared.b16 {%0,%1,%2,%3}, [%4];"
                    : "=r"(r0), "=r"(r1), "=r"(r2), "=r"(r3)
                    : "r"(Bb + adB0[q] + (uint32_t)kc * 2048u));
                br[2 * q][0] = r0; br[2 * q][1] = r1;
                br[2 * q + 1][0] = r2; br[2 * q + 1][1] = r3;
            }
            #pragma unroll
            for (int j = 0; j < 2; j++) {
                uint32_t a0, a1, a2, a3;
                asm volatile(
                    "ldmatrix.sync.aligned.m8n8.x4.shared.b16 {%0,%1,%2,%3}, [%4];"
                    : "=r"(a0), "=r"(a1), "=r"(a2), "=r"(a3)
                    : "r"(Ab + adA[j][kc]));
                #pragma unroll
                for (int nt = 0; nt < 8; nt++) {
                    asm volatile(
                        "mma.sync.aligned.m16n8k16.row.col.f32.f16.f16.f32 "
                        "{%0,%1,%2,%3},{%4,%5,%6,%7},{%8,%9},{%0,%1,%2,%3};"
                        : "+f"(acc[j][nt][0]), "+f"(acc[j][nt][1]),
                          "+f"(acc[j][nt][2]), "+f"(acc[j][nt][3])
                        : "r"(a0), "r"(a1), "r"(a2), "r"(a3),
                          "r"(br[nt][0]), "r"(br[nt][1]));
                }
            }
        }
        __syncthreads();
    }

    // ---- epilogue: scatter acc to g_conv[d][b][co][oh][ow] ----
    #pragma unroll
    for (int j = 0; j < 2; j++) {
        int r0 = 32 * w + 16 * j + (lane >> 2);
        #pragma unroll
        for (int hh = 0; hh < 2; hh++) {
            int s = tile * 256 + r0 + 8 * hh;
            int bb = s / 2304, rem = s % 2304;
            int oh = rem / 48, ow = rem % 48;
            float* p = g_conv + (((size_t)(dIdx * NB + bb) * NCO) * HW + oh) * HW + ow;
            #pragma unroll
            for (int nt = 0; nt < 8; nt++) {
                int co = nt * 8 + (lane & 3) * 2;
                p[(size_t)co * (HW * HW)]       = acc[j][nt][2 * hh];
                p[(size_t)(co + 1) * (HW * HW)] = acc[j][nt][2 * hh + 1];
            }
        }
    }
}

// ---------------------------------------------------------------------------
// Kernel E: assemble cost volume [B, CO, 68, 48, 48].
// ---------------------------------------------------------------------------
__global__ void assemble_kernel(float* __restrict__ out) {
    const int total = NB * NCO * 17 * HW * (HW / 4);
    int idx = blockIdx.x * 256 + threadIdx.x;
    if (idx >= total) return;
    int w4 = idx % 12; int t = idx / 12;
    int oh = t % 48;   t /= 48;
    int i  = t % 17;   t /= 17;
    int co = t % 64;   int b = t / 64;

    float4 val = make_float4(0.f, 0.f, 0.f, 0.f);
    if (i & 1) {
        int p = (i - 1) >> 1;
        const float* base1 = g_conv +
            (((size_t)(p * NB + b) * NCO + co) * HW + oh) * HW;
        const float* base2 = base1 + (size_t)NB * NCO * HW * HW;
        float4 a = ((const float4*)base1)[w4];
        float4 c = ((const float4*)base2)[w4];
        val = make_float4(0.5f * (a.x + c.x), 0.5f * (a.y + c.y),
                          0.5f * (a.z + c.z), 0.5f * (a.w + c.w));
    }
    float4* o = (float4*)(out +
        ((((size_t)b * NCO + co) * 68 + 4 * i) * HW + oh) * HW) + w4;
    o[0]    = val;
    o[576]  = val;
    o[1152] = val;
    o[1728] = val;
}

// ---------------------------------------------------------------------------
extern "C" void kernel_launch(void* const* d_in, const int* in_sizes, int n_in,
                              void* d_out, int out_size) {
    const float* x = (const float*)d_in[0];
    const float* w = (const float*)d_in[1];
    if (n_in >= 2 && in_sizes[0] < in_sizes[1]) {
        const float* tmp = x; x = w; w = tmp;
    }
    cudaFuncSetAttribute(conv_kernel,
                         cudaFuncAttributeMaxDynamicSharedMemorySize, CONV_SMEM);
    reorg_kernel<<<dim3(432, NB), 256>>>(x);
    wprep_kernel<<<(81 * NCI * NCO + 255) / 256, 256>>>(w);
    conv_kernel<<<dim3(ND, NTILES), 256, CONV_SMEM>>>();
    assemble_kernel<<<(NB * NCO * 17 * HW * (HW / 4) + 255) / 256, 256>>>((float*)d_out);
}